// round 14
// baseline (speedup 1.0000x reference)
#include <cuda_runtime.h>
#include <cuda_bf16.h>
#include <cstdint>

// Shapes (fixed by the problem)
constexpr int BB = 64;    // batch
constexpr int KK = 256;   // feature dim K
constexpr int TT = 64;    // word tokens
constexpr int DFE = 768;  // image channels
constexpr int NN = 1024;  // regions

// Scratch (device globals: allocation-free contract)
__device__ float g_s[BB * TT * NN];    // s (pre-softmax)  [B,T,N]
__device__ float g_c[BB * KK * TT];    // c                [B,K,T]
// pre-split bf16 hi/lo planes
__device__ __nv_bfloat16 g_wh[DFE * KK],  g_wl[DFE * KK];    // W    [DF,K]
__device__ __nv_bfloat16 g_wth[KK * DFE], g_wtl[KK * DFE];   // W^T  [K,DF]
__device__ __nv_bfloat16 g_eh[BB * KK * TT], g_el[BB * KK * TT];   // e
__device__ __nv_bfloat16 g_uh[BB * TT * DFE], g_ul[BB * TT * DFE]; // u'
__device__ __nv_bfloat16 g_ah[BB * TT * NN], g_al[BB * TT * NN];   // alpha
__device__ __nv_bfloat16 g_gh[BB * DFE * TT], g_gl[BB * DFE * TT]; // g

typedef unsigned int u32;

// ---- helpers --------------------------------------------------------------
__device__ __forceinline__ u32 smem_u32(const void* p) {
    u32 a;
    asm("{ .reg .u64 t; cvta.to.shared.u64 t, %1; cvt.u32.u64 %0, t; }"
        : "=r"(a) : "l"(p));
    return a;
}
// pack (a->low16, b->high16) bf16x2
__device__ __forceinline__ u32 pack_bf2(float a, float b) {
    u32 r; asm("cvt.rn.bf16x2.f32 %0, %1, %2;" : "=r"(r) : "f"(b), "f"(a));
    return r;
}
__device__ __forceinline__ float bflo(u32 p) { return __uint_as_float(p << 16); }
__device__ __forceinline__ float bfhi(u32 p) { return __uint_as_float(p & 0xffff0000u); }

// split 8 consecutive fp32 (two float4) into bf16x2 hi/lo uint4
__device__ __forceinline__ void split8(float4 x0, float4 x1, uint4& h, uint4& l) {
    h.x = pack_bf2(x0.x, x0.y);
    h.y = pack_bf2(x0.z, x0.w);
    h.z = pack_bf2(x1.x, x1.y);
    h.w = pack_bf2(x1.z, x1.w);
    l.x = pack_bf2(x0.x - bflo(h.x), x0.y - bfhi(h.x));
    l.y = pack_bf2(x0.z - bflo(h.y), x0.w - bfhi(h.y));
    l.z = pack_bf2(x1.x - bflo(h.z), x1.y - bfhi(h.z));
    l.w = pack_bf2(x1.z - bflo(h.w), x1.w - bfhi(h.w));
}
__device__ __forceinline__ void st_split(__nv_bfloat16* H, __nv_bfloat16* L,
                                         long idx, float v) {
    __nv_bfloat16 h = __float2bfloat16(v);
    H[idx] = h;
    L[idx] = __float2bfloat16(v - __bfloat162float(h));
}

__device__ __forceinline__ void cp16(u32 dst, const void* src) {
    asm volatile("cp.async.ca.shared.global [%0], [%1], 16;"
                 :: "r"(dst), "l"(src));
}
#define CP_COMMIT() asm volatile("cp.async.commit_group;")
#define CP_WAIT1()  asm volatile("cp.async.wait_group 1;")
#define CP_WAIT0()  asm volatile("cp.async.wait_group 0;")

__device__ __forceinline__ void ldsm4(u32* r, u32 addr) {
    asm volatile("ldmatrix.sync.aligned.m8n8.x4.shared.b16 {%0,%1,%2,%3}, [%4];"
                 : "=r"(r[0]), "=r"(r[1]), "=r"(r[2]), "=r"(r[3]) : "r"(addr));
}
__device__ __forceinline__ void ldsm4t(u32* r, u32 addr) {
    asm volatile("ldmatrix.sync.aligned.m8n8.x4.trans.shared.b16 {%0,%1,%2,%3}, [%4];"
                 : "=r"(r[0]), "=r"(r[1]), "=r"(r[2]), "=r"(r[3]) : "r"(addr));
}
__device__ __forceinline__ void mma_bf16(float* d, const u32* a, const u32* b) {
    asm volatile(
        "mma.sync.aligned.m16n8k16.row.col.f32.bf16.bf16.f32 "
        "{%0,%1,%2,%3}, {%4,%5,%6,%7}, {%8,%9}, {%0,%1,%2,%3};"
        : "+f"(d[0]), "+f"(d[1]), "+f"(d[2]), "+f"(d[3])
        : "r"(a[0]), "r"(a[1]), "r"(a[2]), "r"(a[3]), "r"(b[0]), "r"(b[1]));
}

// Stage layout A8K+B4K kernels (u,c): Ah 0 | Al 8192 | Bh 16384 | Bl 20480
// Stage layout s_mma:                 Ah 0 | Al 4096 | Bh 8192(2x4K) | Bl 16384
constexpr int STG = 24576;

// ---------------------------------------------------------------------------
// prep_w: W [DF,K] -> split planes for W and W^T
// ---------------------------------------------------------------------------
__global__ void prep_w(const float* __restrict__ W) {
    int idx = blockIdx.x * 256 + threadIdx.x;   // DFE*KK
    int d = idx >> 8, k = idx & 255;
    float v = W[idx];
    __nv_bfloat16 h = __float2bfloat16(v);
    __nv_bfloat16 lo = __float2bfloat16(v - __bfloat162float(h));
    g_wh[idx] = h;  g_wl[idx] = lo;
    g_wth[k * DFE + d] = h;  g_wtl[k * DFE + d] = lo;
}
// prep_e: e [B,K,T] -> split planes
__global__ void prep_e(const float* __restrict__ E) {
    int idx = blockIdx.x * 256 + threadIdx.x;   // BB*KK*TT
    float v = E[idx];
    __nv_bfloat16 h = __float2bfloat16(v);
    g_eh[idx] = h;
    g_el[idx] = __float2bfloat16(v - __bfloat162float(h));
}

// ---------------------------------------------------------------------------
// u_mma: u[d][t] = sum_k W[d][k] e[k][t]; store split-transposed u'[t][d].
// CTA 128d x 64t, K chunks of 32. All staging via cp.async from planes.
// ---------------------------------------------------------------------------
__global__ __launch_bounds__(256) void u_mma()
{
    __shared__ __align__(16) char sm[2][STG];
    const int b = blockIdx.z;
    const int d0 = blockIdx.x * 128;
    const int tid = threadIdx.x;
    const int warp = tid >> 5, l = tid & 31;
    const int wm = warp >> 1, wn = warp & 1;
    const u32 smb = smem_u32(sm);

    float acc[2][4][4] = {};

    auto cp_issue = [&](int st, int k0) {
        u32 sb_ = smb + st * STG;
#pragma unroll
        for (int it = 0; it < 2; it++) {
            int i = it * 256 + tid;
            int r = i >> 2, gq = i & 3;
            u32 dst = sb_ + r * 64 + ((gq ^ ((r >> 1) & 3)) << 4);
            long src = (long)(d0 + r) * KK + k0 + gq * 8;
            cp16(dst,        &g_wh[src]);
            cp16(dst + 8192, &g_wl[src]);
        }
        {
            int k = tid >> 3, g = tid & 7;
            u32 dst = sb_ + 16384 + k * 128 + ((g ^ (k & 7)) << 4);
            long src = ((long)b * KK + k0 + k) * TT + g * 8;
            cp16(dst,        &g_eh[src]);
            cp16(dst + 4096, &g_el[src]);
        }
        CP_COMMIT();
    };

    cp_issue(0, 0);
    for (int ch = 0; ch < KK / 32; ch++) {
        int st = ch & 1;
        if (ch + 1 < KK / 32) { cp_issue(st ^ 1, (ch + 1) * 32); CP_WAIT1(); }
        else CP_WAIT0();
        __syncthreads();
        u32 ab = smb + st * STG;
#pragma unroll
        for (int kk = 0; kk < 2; kk++) {
            u32 Ah[2][4], Alo[2][4], Bh[2][4], Bl[2][4];
#pragma unroll
            for (int mf = 0; mf < 2; mf++) {
                int r = wm * 32 + mf * 16 + (l & 7) + ((l >> 3) & 1) * 8;
                int cA = kk * 2 + (l >> 4);
                u32 off = r * 64 + ((cA ^ ((r >> 1) & 3)) << 4);
                ldsm4(Ah[mf],  ab + off);
                ldsm4(Alo[mf], ab + 8192 + off);
            }
            int rB = kk * 16 + (l & 7) + ((l >> 3) & 1) * 8;
#pragma unroll
            for (int nf2 = 0; nf2 < 2; nf2++) {
                int cB = wn * 4 + nf2 * 2 + (l >> 4);
                u32 offb = rB * 128 + ((cB ^ (rB & 7)) << 4);
                ldsm4t(Bh[nf2], ab + 16384 + offb);
                ldsm4t(Bl[nf2], ab + 20480 + offb);
            }
#pragma unroll
            for (int mf = 0; mf < 2; mf++)
#pragma unroll
                for (int nf = 0; nf < 4; nf++) {
                    int n2 = nf >> 1, j = nf & 1;
                    mma_bf16(acc[mf][nf], Ah[mf],  &Bh[n2][j * 2]);
                    mma_bf16(acc[mf][nf], Ah[mf],  &Bl[n2][j * 2]);
                    mma_bf16(acc[mf][nf], Alo[mf], &Bh[n2][j * 2]);
                }
        }
        __syncthreads();
    }

    const int g8 = l >> 2, tig = l & 3;
#pragma unroll
    for (int mf = 0; mf < 2; mf++)
#pragma unroll
        for (int nf = 0; nf < 4; nf++) {
            int m = wm * 32 + mf * 16 + g8;
            int t0 = wn * 32 + nf * 8 + tig * 2;
            long base_ = ((long)b * TT + t0) * DFE + d0 + m;
            st_split(g_uh, g_ul, base_,           acc[mf][nf][0]);
            st_split(g_uh, g_ul, base_ + DFE,     acc[mf][nf][1]);
            st_split(g_uh, g_ul, base_ + 8,       acc[mf][nf][2]);
            st_split(g_uh, g_ul, base_ + DFE + 8, acc[mf][nf][3]);
        }
}

// ---------------------------------------------------------------------------
// s_mma: s[t][n] = sum_d u'[t][d] f[d][n].  CTA 64t x 128n, 24 chunks of 32.
// A = u' planes via cp.async (SW64); B = f fp32 LDG+split8+STS.128 (SW128x2)
// (best-measured R11 configuration: no minblocks cap)
// ---------------------------------------------------------------------------
__global__ __launch_bounds__(256) void s_mma(const float* __restrict__ F,
                                             float* __restrict__ S)
{
    __shared__ __align__(16) char sm[2][STG];
    const int b  = blockIdx.z;
    const int n0 = blockIdx.x * 128;
    const float* Fb = F + (long)b * DFE * NN;
    const __nv_bfloat16* Uhb = g_uh + (long)b * TT * DFE;
    const __nv_bfloat16* Ulb = g_ul + (long)b * TT * DFE;
    const int tid = threadIdx.x;
    const int warp = tid >> 5, l = tid & 31;
    const int wm = warp >> 2, wn = warp & 3;
    const u32 smb = smem_u32(sm);

    float4 rf[4];
    float acc[2][4][4] = {};

    auto ldg_f = [&](int dc) {
#pragma unroll
        for (int it = 0; it < 2; it++) {
            int i = it * 256 + tid;
            int k = i >> 4, grp = i & 15;
            const float* src = &Fb[(long)(dc + k) * NN + n0 + grp * 8];
            rf[it * 2]     = *(const float4*)src;
            rf[it * 2 + 1] = *(const float4*)(src + 4);
        }
    };
    auto sts_f = [&](int st) {
        char* base = sm[st];
#pragma unroll
        for (int it = 0; it < 2; it++) {
            int i = it * 256 + tid;
            int k = i >> 4, grp = i & 15;
            int sb2 = grp >> 3, g = grp & 7;
            uint4 hv, lv;
            split8(rf[it * 2], rf[it * 2 + 1], hv, lv);
            u32 off = 8192 + sb2 * 4096 + k * 128 + ((g ^ (k & 7)) << 4);
            *(uint4*)(base + off)        = hv;
            *(uint4*)(base + off + 8192) = lv;
        }
    };
    auto cp_u = [&](int st, int dc) {
        u32 sb_ = smb + st * STG;
        int r = tid >> 2, gq = tid & 3;
        u32 dst = sb_ + r * 64 + ((gq ^ ((r >> 1) & 3)) << 4);
        long src = (long)r * DFE + dc + gq * 8;
        cp16(dst,        &Uhb[src]);
        cp16(dst + 4096, &Ulb[src]);
        CP_COMMIT();
    };

    ldg_f(0);
    cp_u(0, 0);
    for (int ch = 0; ch < DFE / 32; ch++) {
        int st = ch & 1;
        sts_f(st);
        if (ch + 1 < DFE / 32) {
            ldg_f((ch + 1) * 32);
            cp_u(st ^ 1, (ch + 1) * 32);
            CP_WAIT1();
        } else CP_WAIT0();
        __syncthreads();
        u32 ab = smb + st * STG;
        u32 bb = ab + 8192 + (wn >> 1) * 4096;
#pragma unroll
        for (int kk = 0; kk < 2; kk++) {
            u32 Ah[2][4], Alo[2][4], Bh[2][4], Bl[2][4];
#pragma unroll
            for (int mf = 0; mf < 2; mf++) {
                int r = wm * 32 + mf * 16 + (l & 7) + ((l >> 3) & 1) * 8;
                int cA = kk * 2 + (l >> 4);
                u32 off = r * 64 + ((cA ^ ((r >> 1) & 3)) << 4);
                ldsm4(Ah[mf],  ab + off);
                ldsm4(Alo[mf], ab + 4096 + off);
            }
            int rB = kk * 16 + (l & 7) + ((l >> 3) & 1) * 8;
#pragma unroll
            for (int nf2 = 0; nf2 < 2; nf2++) {
                int cB = (wn & 1) * 4 + nf2 * 2 + (l >> 4);
                u32 offb = rB * 128 + ((cB ^ (rB & 7)) << 4);
                ldsm4t(Bh[nf2], bb + offb);
                ldsm4t(Bl[nf2], bb + 8192 + offb);
            }
#pragma unroll
            for (int mf = 0; mf < 2; mf++)
#pragma unroll
                for (int nf = 0; nf < 4; nf++) {
                    int n2 = nf >> 1, j = nf & 1;
                    mma_bf16(acc[mf][nf], Ah[mf],  &Bh[n2][j * 2]);
                    mma_bf16(acc[mf][nf], Ah[mf],  &Bl[n2][j * 2]);
                    mma_bf16(acc[mf][nf], Alo[mf], &Bh[n2][j * 2]);
                }
        }
        __syncthreads();
    }

    const int g8 = l >> 2, tig = l & 3;
#pragma unroll
    for (int mf = 0; mf < 2; mf++)
#pragma unroll
        for (int nf = 0; nf < 4; nf++) {
            int t = wm * 32 + mf * 16 + g8;
            int n = n0 + wn * 32 + nf * 8 + tig * 2;
            float* p = &S[((long)b * TT + t) * NN + n];
            *(float2*)p            = make_float2(acc[mf][nf][0], acc[mf][nf][1]);
            *(float2*)(p + 8 * NN) = make_float2(acc[mf][nf][2], acc[mf][nf][3]);
        }
}

// ---------------------------------------------------------------------------
// softmax: alpha = softmax(gamma*s) over N; write alpha as split bf16 planes.
// ---------------------------------------------------------------------------
__global__ __launch_bounds__(256) void softmax_k(const float* __restrict__ S,
                                                 const float* __restrict__ gp)
{
    __shared__ float red[8];
    const long row = blockIdx.x;
    const float* s = S + row * NN;
    const int tid = threadIdx.x;
    const float g = *gp;

    float4 v = *(const float4*)&s[tid * 4];
    v.x *= g; v.y *= g; v.z *= g; v.w *= g;

    float m = fmaxf(fmaxf(v.x, v.y), fmaxf(v.z, v.w));
#pragma unroll
    for (int o = 16; o > 0; o >>= 1) m = fmaxf(m, __shfl_xor_sync(0xffffffffu, m, o));
    if ((tid & 31) == 0) red[tid >> 5] = m;
    __syncthreads();
    m = red[0];
#pragma unroll
    for (int i = 1; i < 8; i++) m = fmaxf(m, red[i]);
    __syncthreads();

    float e0 = __expf(v.x - m), e1 = __expf(v.y - m);
    float e2 = __expf(v.z - m), e3 = __expf(v.w - m);
    float sum = (e0 + e1) + (e2 + e3);
#pragma unroll
    for (int o = 16; o > 0; o >>= 1) sum += __shfl_xor_sync(0xffffffffu, sum, o);
    if ((tid & 31) == 0) red[tid >> 5] = sum;
    __syncthreads();
    sum = ((red[0] + red[1]) + (red[2] + red[3])) +
          ((red[4] + red[5]) + (red[6] + red[7]));
    float r = 1.0f / sum;
    float a0 = e0 * r, a1 = e1 * r, a2 = e2 * r, a3 = e3 * r;

    u32 h0 = pack_bf2(a0, a1), h1 = pack_bf2(a2, a3);
    u32 l0 = pack_bf2(a0 - bflo(h0), a1 - bfhi(h0));
    u32 l1 = pack_bf2(a2 - bflo(h1), a3 - bfhi(h1));
    long off = row * NN + tid * 4;
    *(uint2*)(&g_ah[off]) = make_uint2(h0, h1);
    *(uint2*)(&g_al[off]) = make_uint2(l0, l1);
}

// ---------------------------------------------------------------------------
// g_mma: g[d][t] = sum_n f[d][n] alpha[t][n].  CTA 128d x 64t.
// ZERO-SMEM direct-fragment version: A (f fp32) loaded straight into mma
// fragment layout via float2 LDGs and split to bf16 hi/lo in registers;
// B (alpha bf16 planes) loaded as (k,k+1)-pair u32s directly.
// 64 k16 steps, one-step-ahead register prefetch. No barriers.
// ---------------------------------------------------------------------------
__global__ __launch_bounds__(256) void g_mma(const float* __restrict__ F)
{
    const int b  = blockIdx.z;
    const int d0 = blockIdx.x * 128;
    const float* Fb = F + ((long)b * DFE + d0) * NN;
    const __nv_bfloat16* __restrict__ Ahb = g_ah + (long)b * TT * NN;
    const __nv_bfloat16* __restrict__ Alb = g_al + (long)b * TT * NN;
    const int tid = threadIdx.x;
    const int warp = tid >> 5, l = tid & 31;
    const int wm = warp >> 1, wn = warp & 1;
    const int lr = l >> 2, lc = (l & 3) * 2;

    float acc[2][4][4] = {};

    // A base pointer: row = d0-relative wm*32 + mf*16 + lr, col = step*16 + lc
    const float* pa = Fb + (long)(wm * 32 + lr) * NN + lc;
    // B base offset: t = wn*32 + nf*8 + lr, n = step*16 + lc
    const long tb = (long)(wn * 32 + lr) * NN + lc;

    float2 fa[2][2][4];          // [buf][mf][4 frag pairs]
    u32 bh[2][4][2], bl[2][4][2];// [buf][nf][2]

    auto load_step = [&](int buf, int s) {
        int off = s * 16;
#pragma unroll
        for (int mf = 0; mf < 2; mf++) {
            const float* p = pa + (long)mf * 16 * NN + off;
            fa[buf][mf][0] = *(const float2*)(p);
            fa[buf][mf][1] = *(const float2*)(p + 8 * NN);
            fa[buf][mf][2] = *(const float2*)(p + 8);
            fa[buf][mf][3] = *(const float2*)(p + 8 * NN + 8);
        }
#pragma unroll
        for (int nf = 0; nf < 4; nf++) {
            long t = tb + (long)nf * 8 * NN + off;
            bh[buf][nf][0] = *(const u32*)(Ahb + t);
            bh[buf][nf][1] = *(const u32*)(Ahb + t + 8);
            bl[buf][nf][0] = *(const u32*)(Alb + t);
            bl[buf][nf][1] = *(const u32*)(Alb + t + 8);
        }
    };
    auto compute_step = [&](int buf) {
#pragma unroll
        for (int mf = 0; mf < 2; mf++) {
            u32 Ah[4], Al[4];
#pragma unroll
            for (int q = 0; q < 4; q++) {
                float2 x = fa[buf][mf][q];
                Ah[q] = pack_bf2(x.x, x.y);
                Al[q] = pack_bf2(x.x - bflo(Ah[q]), x.y - bfhi(Ah[q]));
            }
#pragma unroll
            for (int nf = 0; nf < 4; nf++) {
                mma_bf16(acc[mf][nf], Ah, bh[buf][nf]);
                mma_bf16(acc[mf][nf], Ah, bl[buf][nf]);
                mma_bf16(acc[mf][nf], Al, bh[buf][nf]);
            }
        }
    };

    constexpr int NSTEP = NN / 16;   // 64
    load_step(0, 0);
    for (int s = 0; s < NSTEP; s++) {
        if (s + 1 < NSTEP) load_step((s + 1) & 1, s + 1);
        compute_step(s & 1);
    }

    const int g8 = l >> 2, tig = l & 3;
#pragma unroll
    for (int mf = 0; mf < 2; mf++)
#pragma unroll
        for (int nf = 0; nf < 4; nf++) {
            int dd = d0 + wm * 32 + mf * 16 + g8;
            int t  = wn * 32 + nf * 8 + tig * 2;
            long off = ((long)b * DFE + dd) * TT + t;
            u32 h = pack_bf2(acc[mf][nf][0], acc[mf][nf][1]);
            u32 lo = pack_bf2(acc[mf][nf][0] - bflo(h),
                              acc[mf][nf][1] - bfhi(h));
            *(u32*)(&g_gh[off]) = h;
            *(u32*)(&g_gl[off]) = lo;
            long off2 = off + 8 * TT;
            u32 h2 = pack_bf2(acc[mf][nf][2], acc[mf][nf][3]);
            u32 lo2 = pack_bf2(acc[mf][nf][2] - bflo(h2),
                               acc[mf][nf][3] - bfhi(h2));
            *(u32*)(&g_gh[off2]) = h2;
            *(u32*)(&g_gl[off2]) = lo2;
        }
}

// ---------------------------------------------------------------------------
// c_mma: c[m][t] = sum_d wt[m][d] g[d][t] + bias[m].  CTA 128m x 64t.
// A = wt planes (SW64); B = g planes (SW128 trans). All cp.async.
// ---------------------------------------------------------------------------
__global__ __launch_bounds__(256) void c_mma(const float* __restrict__ bias,
                                             float* __restrict__ C)
{
    __shared__ __align__(16) char sm[2][STG];
    const int b  = blockIdx.z;
    const int m0 = blockIdx.x * 128;
    const __nv_bfloat16* Ghb = g_gh + (long)b * DFE * TT;
    const __nv_bfloat16* Glb = g_gl + (long)b * DFE * TT;
    const int tid = threadIdx.x;
    const int warp = tid >> 5, l = tid & 31;
    const int wm = warp >> 1, wn = warp & 1;
    const u32 smb = smem_u32(sm);

    float acc[2][4][4] = {};

    auto cp_issue = [&](int st, int dc) {
        u32 sb_ = smb + st * STG;
#pragma unroll
        for (int it = 0; it < 2; it++) {
            int i = it * 256 + tid;
            int r = i >> 2, gq = i & 3;
            u32 dst = sb_ + r * 64 + ((gq ^ ((r >> 1) & 3)) << 4);
            long src = (long)(m0 + r) * DFE + dc + gq * 8;
            cp16(dst,        &g_wth[src]);
            cp16(dst + 8192, &g_wtl[src]);
        }
        {
            int k = tid >> 3, g = tid & 7;
            u32 dst = sb_ + 16384 + k * 128 + ((g ^ (k & 7)) << 4);
            long src = (long)(dc + k) * TT + g * 8;
            cp16(dst,        &Ghb[src]);
            cp16(dst + 4096, &Glb[src]);
        }
        CP_COMMIT();
    };

    cp_issue(0, 0);
    for (int ch = 0; ch < DFE / 32; ch++) {
        int st = ch & 1;
        if (ch + 1 < DFE / 32) { cp_issue(st ^ 1, (ch + 1) * 32); CP_WAIT1(); }
        else CP_WAIT0();
        __syncthreads();
        u32 ab = smb + st * STG;
#pragma unroll
        for (int kk = 0; kk < 2; kk++) {
            u32 Ah[2][4], Alo[2][4], Bh[2][4], Bl[2][4];
#pragma unroll
            for (int mf = 0; mf < 2; mf++) {
                int r = wm * 32 + mf * 16 + (l & 7) + ((l >> 3) & 1) * 8;
                int cA = kk * 2 + (l >> 4);
                u32 off = r * 64 + ((cA ^ ((r >> 1) & 3)) << 4);
                ldsm4(Ah[mf],  ab + off);
                ldsm4(Alo[mf], ab + 8192 + off);
            }
            int rB = kk * 16 + (l & 7) + ((l >> 3) & 1) * 8;
#pragma unroll
            for (int nf2 = 0; nf2 < 2; nf2++) {
                int cB = wn * 4 + nf2 * 2 + (l >> 4);
                u32 offb = rB * 128 + ((cB ^ (rB & 7)) << 4);
                ldsm4t(Bh[nf2], ab + 16384 + offb);
                ldsm4t(Bl[nf2], ab + 20480 + offb);
            }
#pragma unroll
            for (int mf = 0; mf < 2; mf++)
#pragma unroll
                for (int nf = 0; nf < 4; nf++) {
                    int n2 = nf >> 1, j = nf & 1;
                    mma_bf16(acc[mf][nf], Ah[mf],  &Bh[n2][j * 2]);
                    mma_bf16(acc[mf][nf], Ah[mf],  &Bl[n2][j * 2]);
                    mma_bf16(acc[mf][nf], Alo[mf], &Bh[n2][j * 2]);
                }
        }
        __syncthreads();
    }

    const int g8 = l >> 2, tig = l & 3;
#pragma unroll
    for (int mf = 0; mf < 2; mf++) {
        int row = wm * 32 + mf * 16 + g8;
        float bi0 = bias[m0 + row], bi1 = bias[m0 + row + 8];
#pragma unroll
        for (int nf = 0; nf < 4; nf++) {
            int t0 = wn * 32 + nf * 8 + tig * 2;
            float* p = &C[((long)b * KK + m0 + row) * TT + t0];
            *(float2*)p = make_float2(acc[mf][nf][0] + bi0, acc[mf][nf][1] + bi0);
            *(float2*)(p + 8 * TT) =
                make_float2(acc[mf][nf][2] + bi1, acc[mf][nf][3] + bi1);
        }
    }
}

// ---------------------------------------------------------------------------
// Finalize: norms + cos[b][i][j] = (sum_k c[k][i] e[k][j]) / (lc[i] le[j])
// ---------------------------------------------------------------------------
__global__ __launch_bounds__(256) void finalize_k(const float* __restrict__ Cm,
                                                  const float* __restrict__ E,
                                                  float* __restrict__ Out)
{
    __shared__ float rn[128];
    __shared__ float As[16][64];
    __shared__ float Bs[16][64];
    const int b = blockIdx.x;
    const float* cb = Cm + (long)b * KK * TT;
    const float* eb = E + (long)b * KK * TT;
    const int tid = threadIdx.x;

    if (tid < 128) {
        const float* p = (tid < 64) ? cb : eb;
        int t = tid & 63;
        float ss = 0.f;
        for (int k = 0; k < KK; k++) {
            float x = p[k * TT + t];
            ss = fmaf(x, x, ss);
        }
        rn[tid] = rsqrtf(ss);
    }

    const int tx = tid & 15, ty = tid >> 4;
    float acc[4][4] = {};
    for (int k0 = 0; k0 < KK; k0 += 16) {
        *(float4*)&As[ty][tx * 4] = *(const float4*)&cb[(k0 + ty) * TT + tx * 4];
        *(float4*)&Bs[ty][tx * 4] = *(const float4*)&eb[(k0 + ty) * TT + tx * 4];
        __syncthreads();
#pragma unroll
        for (int kk = 0; kk < 16; kk++) {
            float4 a4 = *(const float4*)&As[kk][ty * 4];
            float4 b4 = *(const float4*)&Bs[kk][tx * 4];
            float av[4] = {a4.x, a4.y, a4.z, a4.w};
            float bv[4] = {b4.x, b4.y, b4.z, b4.w};
#pragma unroll
            for (int i = 0; i < 4; i++)
#pragma unroll
                for (int j = 0; j < 4; j++) acc[i][j] = fmaf(av[i], bv[j], acc[i][j]);
        }
        __syncthreads();
    }

    float* ob = Out + (long)b * TT * TT;
#pragma unroll
    for (int i = 0; i < 4; i++) {
        int ii = ty * 4 + i;
        float ri = rn[ii];
        float4 o;
        o.x = acc[i][0] * ri * rn[64 + tx * 4 + 0];
        o.y = acc[i][1] * ri * rn[64 + tx * 4 + 1];
        o.z = acc[i][2] * ri * rn[64 + tx * 4 + 2];
        o.w = acc[i][3] * ri * rn[64 + tx * 4 + 3];
        *(float4*)&ob[ii * TT + tx * 4] = o;
    }
}

// ---------------------------------------------------------------------------
extern "C" void kernel_launch(void* const* d_in, const int* in_sizes, int n_in,
                              void* d_out, int out_size)
{
    const float* e  = (const float*)d_in[0];   // [B,K,T]
    const float* f  = (const float*)d_in[1];   // [B,DF,N]
    const float* gp = (const float*)d_in[2];   // scalar gamma
    const float* W  = (const float*)d_in[3];   // [DF,K]
    const float* bs = (const float*)d_in[4];   // [K]
    float* out = (float*)d_out;                // [B,T,T]

    float *ps, *pc;
    cudaGetSymbolAddress((void**)&ps, g_s);
    cudaGetSymbolAddress((void**)&pc, g_c);

    // 0) split W / W^T / e into bf16 hi-lo planes
    prep_w<<<DFE * KK / 256, 256>>>(W);
    prep_e<<<BB * KK * TT / 256, 256>>>(e);

    // 1) u' = (W e)^T -> split planes [B,T,DF]  (bias cancels in softmax)
    u_mma<<<dim3(DFE / 128, 1, BB), 256>>>();

    // 2) s = u' f : [B,T,N] fp32
    s_mma<<<dim3(NN / 128, 1, BB), 256>>>(f, ps);

    // 3) alpha = softmax(gamma * s) -> split planes
    softmax_k<<<BB * TT, 256>>>(ps, gp);

    // 4) g = f alpha^T -> split planes [B,DF,T]  (zero-smem direct fragments)
    g_mma<<<dim3(DFE / 128, 1, BB), 256>>>(f);

    // 5) c = W^T g + b : [B,K,T] fp32  (Sum_n alpha = 1)
    c_mma<<<dim3(KK / 128, 1, BB), 256>>>(bs, pc);

    // 6) cos = (c^T e) / outer(|c|,|e|)
    finalize_k<<<64, 256>>>(pc, e, out);
}

// round 15
// speedup vs baseline: 1.8760x; 1.8760x over previous
#include <cuda_runtime.h>
#include <cuda_bf16.h>
#include <cstdint>

// Shapes (fixed by the problem)
constexpr int BB = 64;    // batch
constexpr int KK = 256;   // feature dim K
constexpr int TT = 64;    // word tokens
constexpr int DFE = 768;  // image channels
constexpr int NN = 1024;  // regions

// Scratch (device globals: allocation-free contract)
__device__ float g_s[BB * TT * NN];    // s (pre-softmax)  [B,T,N]
__device__ float g_c[BB * KK * TT];    // c                [B,K,T]
// pre-split bf16 hi/lo planes
__device__ __nv_bfloat16 g_wh[DFE * KK],  g_wl[DFE * KK];    // W    [DF,K]
__device__ __nv_bfloat16 g_wth[KK * DFE], g_wtl[KK * DFE];   // W^T  [K,DF]
__device__ __nv_bfloat16 g_eh[BB * KK * TT], g_el[BB * KK * TT];   // e
__device__ __nv_bfloat16 g_uh[BB * TT * DFE], g_ul[BB * TT * DFE]; // u'
__device__ __nv_bfloat16 g_ah[BB * TT * NN], g_al[BB * TT * NN];   // alpha
__device__ __nv_bfloat16 g_gh[BB * DFE * TT], g_gl[BB * DFE * TT]; // g

typedef unsigned int u32;

// ---- helpers --------------------------------------------------------------
__device__ __forceinline__ u32 smem_u32(const void* p) {
    u32 a;
    asm("{ .reg .u64 t; cvta.to.shared.u64 t, %1; cvt.u32.u64 %0, t; }"
        : "=r"(a) : "l"(p));
    return a;
}
// pack (a->low16, b->high16) bf16x2
__device__ __forceinline__ u32 pack_bf2(float a, float b) {
    u32 r; asm("cvt.rn.bf16x2.f32 %0, %1, %2;" : "=r"(r) : "f"(b), "f"(a));
    return r;
}
__device__ __forceinline__ float bflo(u32 p) { return __uint_as_float(p << 16); }
__device__ __forceinline__ float bfhi(u32 p) { return __uint_as_float(p & 0xffff0000u); }

// split 8 consecutive fp32 (two float4) into bf16x2 hi/lo uint4
__device__ __forceinline__ void split8(float4 x0, float4 x1, uint4& h, uint4& l) {
    h.x = pack_bf2(x0.x, x0.y);
    h.y = pack_bf2(x0.z, x0.w);
    h.z = pack_bf2(x1.x, x1.y);
    h.w = pack_bf2(x1.z, x1.w);
    l.x = pack_bf2(x0.x - bflo(h.x), x0.y - bfhi(h.x));
    l.y = pack_bf2(x0.z - bflo(h.y), x0.w - bfhi(h.y));
    l.z = pack_bf2(x1.x - bflo(h.z), x1.y - bfhi(h.z));
    l.w = pack_bf2(x1.z - bflo(h.w), x1.w - bfhi(h.w));
}
__device__ __forceinline__ void st_split(__nv_bfloat16* H, __nv_bfloat16* L,
                                         long idx, float v) {
    __nv_bfloat16 h = __float2bfloat16(v);
    H[idx] = h;
    L[idx] = __float2bfloat16(v - __bfloat162float(h));
}

__device__ __forceinline__ void cp16(u32 dst, const void* src) {
    asm volatile("cp.async.ca.shared.global [%0], [%1], 16;"
                 :: "r"(dst), "l"(src));
}
#define CP_COMMIT() asm volatile("cp.async.commit_group;")
#define CP_WAIT1()  asm volatile("cp.async.wait_group 1;")
#define CP_WAIT0()  asm volatile("cp.async.wait_group 0;")

__device__ __forceinline__ void ldsm4(u32* r, u32 addr) {
    asm volatile("ldmatrix.sync.aligned.m8n8.x4.shared.b16 {%0,%1,%2,%3}, [%4];"
                 : "=r"(r[0]), "=r"(r[1]), "=r"(r[2]), "=r"(r[3]) : "r"(addr));
}
__device__ __forceinline__ void ldsm4t(u32* r, u32 addr) {
    asm volatile("ldmatrix.sync.aligned.m8n8.x4.trans.shared.b16 {%0,%1,%2,%3}, [%4];"
                 : "=r"(r[0]), "=r"(r[1]), "=r"(r[2]), "=r"(r[3]) : "r"(addr));
}
__device__ __forceinline__ void mma_bf16(float* d, const u32* a, const u32* b) {
    asm volatile(
        "mma.sync.aligned.m16n8k16.row.col.f32.bf16.bf16.f32 "
        "{%0,%1,%2,%3}, {%4,%5,%6,%7}, {%8,%9}, {%0,%1,%2,%3};"
        : "+f"(d[0]), "+f"(d[1]), "+f"(d[2]), "+f"(d[3])
        : "r"(a[0]), "r"(a[1]), "r"(a[2]), "r"(a[3]), "r"(b[0]), "r"(b[1]));
}

// Stage layout A8K+B4K kernels (u,c,g): Ah 0 | Al 8192 | Bh 16384 | Bl 20480
// Stage layout s_mma:                   Ah 0 | Al 4096 | Bh 8192(2x4K) | Bl 16384
constexpr int STG = 24576;

// ---------------------------------------------------------------------------
// prep_w: W [DF,K] -> split planes for W and W^T
// ---------------------------------------------------------------------------
__global__ void prep_w(const float* __restrict__ W) {
    int idx = blockIdx.x * 256 + threadIdx.x;   // DFE*KK
    int d = idx >> 8, k = idx & 255;
    float v = W[idx];
    __nv_bfloat16 h = __float2bfloat16(v);
    __nv_bfloat16 lo = __float2bfloat16(v - __bfloat162float(h));
    g_wh[idx] = h;  g_wl[idx] = lo;
    g_wth[k * DFE + d] = h;  g_wtl[k * DFE + d] = lo;
}
// prep_e: e [B,K,T] -> split planes
__global__ void prep_e(const float* __restrict__ E) {
    int idx = blockIdx.x * 256 + threadIdx.x;   // BB*KK*TT
    float v = E[idx];
    __nv_bfloat16 h = __float2bfloat16(v);
    g_eh[idx] = h;
    g_el[idx] = __float2bfloat16(v - __bfloat162float(h));
}

// ---------------------------------------------------------------------------
// u_mma: u[d][t] = sum_k W[d][k] e[k][t]; store split-transposed u'[t][d].
// CTA 128d x 64t, K chunks of 32. All staging via cp.async from planes.
// ---------------------------------------------------------------------------
__global__ __launch_bounds__(256) void u_mma()
{
    __shared__ __align__(16) char sm[2][STG];
    const int b = blockIdx.z;
    const int d0 = blockIdx.x * 128;
    const int tid = threadIdx.x;
    const int warp = tid >> 5, l = tid & 31;
    const int wm = warp >> 1, wn = warp & 1;
    const u32 smb = smem_u32(sm);

    float acc[2][4][4] = {};

    auto cp_issue = [&](int st, int k0) {
        u32 sb_ = smb + st * STG;
#pragma unroll
        for (int it = 0; it < 2; it++) {
            int i = it * 256 + tid;
            int r = i >> 2, gq = i & 3;
            u32 dst = sb_ + r * 64 + ((gq ^ ((r >> 1) & 3)) << 4);
            long src = (long)(d0 + r) * KK + k0 + gq * 8;
            cp16(dst,        &g_wh[src]);
            cp16(dst + 8192, &g_wl[src]);
        }
        {
            int k = tid >> 3, g = tid & 7;
            u32 dst = sb_ + 16384 + k * 128 + ((g ^ (k & 7)) << 4);
            long src = ((long)b * KK + k0 + k) * TT + g * 8;
            cp16(dst,        &g_eh[src]);
            cp16(dst + 4096, &g_el[src]);
        }
        CP_COMMIT();
    };

    cp_issue(0, 0);
    for (int ch = 0; ch < KK / 32; ch++) {
        int st = ch & 1;
        if (ch + 1 < KK / 32) { cp_issue(st ^ 1, (ch + 1) * 32); CP_WAIT1(); }
        else CP_WAIT0();
        __syncthreads();
        u32 ab = smb + st * STG;
#pragma unroll
        for (int kk = 0; kk < 2; kk++) {
            u32 Ah[2][4], Alo[2][4], Bh[2][4], Bl[2][4];
#pragma unroll
            for (int mf = 0; mf < 2; mf++) {
                int r = wm * 32 + mf * 16 + (l & 7) + ((l >> 3) & 1) * 8;
                int cA = kk * 2 + (l >> 4);
                u32 off = r * 64 + ((cA ^ ((r >> 1) & 3)) << 4);
                ldsm4(Ah[mf],  ab + off);
                ldsm4(Alo[mf], ab + 8192 + off);
            }
            int rB = kk * 16 + (l & 7) + ((l >> 3) & 1) * 8;
#pragma unroll
            for (int nf2 = 0; nf2 < 2; nf2++) {
                int cB = wn * 4 + nf2 * 2 + (l >> 4);
                u32 offb = rB * 128 + ((cB ^ (rB & 7)) << 4);
                ldsm4t(Bh[nf2], ab + 16384 + offb);
                ldsm4t(Bl[nf2], ab + 20480 + offb);
            }
#pragma unroll
            for (int mf = 0; mf < 2; mf++)
#pragma unroll
                for (int nf = 0; nf < 4; nf++) {
                    int n2 = nf >> 1, j = nf & 1;
                    mma_bf16(acc[mf][nf], Ah[mf],  &Bh[n2][j * 2]);
                    mma_bf16(acc[mf][nf], Ah[mf],  &Bl[n2][j * 2]);
                    mma_bf16(acc[mf][nf], Alo[mf], &Bh[n2][j * 2]);
                }
        }
        __syncthreads();
    }

    const int g8 = l >> 2, tig = l & 3;
#pragma unroll
    for (int mf = 0; mf < 2; mf++)
#pragma unroll
        for (int nf = 0; nf < 4; nf++) {
            int m = wm * 32 + mf * 16 + g8;
            int t0 = wn * 32 + nf * 8 + tig * 2;
            long base_ = ((long)b * TT + t0) * DFE + d0 + m;
            st_split(g_uh, g_ul, base_,           acc[mf][nf][0]);
            st_split(g_uh, g_ul, base_ + DFE,     acc[mf][nf][1]);
            st_split(g_uh, g_ul, base_ + 8,       acc[mf][nf][2]);
            st_split(g_uh, g_ul, base_ + DFE + 8, acc[mf][nf][3]);
        }
}

// ---------------------------------------------------------------------------
// s_mma: s[t][n] = sum_d u'[t][d] f[d][n].  CTA 64t x 128n, 24 chunks of 32.
// 128 threads / 4 warps tiled 2x2, warp tile 32t x 64n:
//   A-fragment redundancy 2x (was 4x), B 2x  -> 18% less L1 traffic,
//   identical smem layouts and arithmetic order (bitwise-same result).
// ---------------------------------------------------------------------------
__global__ __launch_bounds__(128) void s_mma(const float* __restrict__ F,
                                             float* __restrict__ S)
{
    __shared__ __align__(16) char sm[2][STG];
    const int b  = blockIdx.z;
    const int n0 = blockIdx.x * 128;
    const float* Fb = F + (long)b * DFE * NN;
    const __nv_bfloat16* Uhb = g_uh + (long)b * TT * DFE;
    const __nv_bfloat16* Ulb = g_ul + (long)b * TT * DFE;
    const int tid = threadIdx.x;
    const int warp = tid >> 5, l = tid & 31;
    const int wm = warp >> 1, wn = warp & 1;   // 2x2
    const u32 smb = smem_u32(sm);

    float4 rf[8];
    float acc[2][8][4] = {};

    auto ldg_f = [&](int dc) {
#pragma unroll
        for (int it = 0; it < 4; it++) {
            int i = it * 128 + tid;
            int k = i >> 4, grp = i & 15;
            const float* src = &Fb[(long)(dc + k) * NN + n0 + grp * 8];
            rf[it * 2]     = *(const float4*)src;
            rf[it * 2 + 1] = *(const float4*)(src + 4);
        }
    };
    auto sts_f = [&](int st) {
        char* base = sm[st];
#pragma unroll
        for (int it = 0; it < 4; it++) {
            int i = it * 128 + tid;
            int k = i >> 4, grp = i & 15;
            int sb2 = grp >> 3, g = grp & 7;
            uint4 hv, lv;
            split8(rf[it * 2], rf[it * 2 + 1], hv, lv);
            u32 off = 8192 + sb2 * 4096 + k * 128 + ((g ^ (k & 7)) << 4);
            *(uint4*)(base + off)        = hv;
            *(uint4*)(base + off + 8192) = lv;
        }
    };
    auto cp_u = [&](int st, int dc) {
        u32 sb_ = smb + st * STG;
#pragma unroll
        for (int it = 0; it < 2; it++) {
            int i = it * 128 + tid;
            int r = i >> 2, gq = i & 3;
            u32 dst = sb_ + r * 64 + ((gq ^ ((r >> 1) & 3)) << 4);
            long src = (long)r * DFE + dc + gq * 8;
            cp16(dst,        &Uhb[src]);
            cp16(dst + 4096, &Ulb[src]);
        }
        CP_COMMIT();
    };

    ldg_f(0);
    cp_u(0, 0);
    for (int ch = 0; ch < DFE / 32; ch++) {
        int st = ch & 1;
        sts_f(st);
        if (ch + 1 < DFE / 32) {
            ldg_f((ch + 1) * 32);
            cp_u(st ^ 1, (ch + 1) * 32);
            CP_WAIT1();
        } else CP_WAIT0();
        __syncthreads();
        u32 ab = smb + st * STG;
        u32 bb = ab + 8192 + wn * 4096;          // this warp's n64 sub-tile
#pragma unroll
        for (int kk = 0; kk < 2; kk++) {
            u32 Ah[2][4], Alo[2][4], Bh[4][4], Bl[4][4];
#pragma unroll
            for (int mf = 0; mf < 2; mf++) {
                int r = wm * 32 + mf * 16 + (l & 7) + ((l >> 3) & 1) * 8;
                int cA = kk * 2 + (l >> 4);
                u32 off = r * 64 + ((cA ^ ((r >> 1) & 3)) << 4);
                ldsm4(Ah[mf],  ab + off);
                ldsm4(Alo[mf], ab + 4096 + off);
            }
            int rB = kk * 16 + (l & 7) + ((l >> 3) & 1) * 8;
#pragma unroll
            for (int nf2 = 0; nf2 < 4; nf2++) {
                int cB = nf2 * 2 + (l >> 4);
                u32 offb = rB * 128 + ((cB ^ (rB & 7)) << 4);
                ldsm4t(Bh[nf2], bb + offb);
                ldsm4t(Bl[nf2], bb + 8192 + offb);
            }
#pragma unroll
            for (int mf = 0; mf < 2; mf++)
#pragma unroll
                for (int nf = 0; nf < 8; nf++) {
                    int n2 = nf >> 1, j = nf & 1;
                    mma_bf16(acc[mf][nf], Ah[mf],  &Bh[n2][j * 2]);
                    mma_bf16(acc[mf][nf], Ah[mf],  &Bl[n2][j * 2]);
                    mma_bf16(acc[mf][nf], Alo[mf], &Bh[n2][j * 2]);
                }
        }
        __syncthreads();
    }

    const int g8 = l >> 2, tig = l & 3;
#pragma unroll
    for (int mf = 0; mf < 2; mf++)
#pragma unroll
        for (int nf = 0; nf < 8; nf++) {
            int t = wm * 32 + mf * 16 + g8;
            int n = n0 + wn * 64 + nf * 8 + tig * 2;
            float* p = &S[((long)b * TT + t) * NN + n];
            *(float2*)p            = make_float2(acc[mf][nf][0], acc[mf][nf][1]);
            *(float2*)(p + 8 * NN) = make_float2(acc[mf][nf][2], acc[mf][nf][3]);
        }
}

// ---------------------------------------------------------------------------
// softmax: alpha = softmax(gamma*s) over N; write alpha as split bf16 planes.
// ---------------------------------------------------------------------------
__global__ __launch_bounds__(256) void softmax_k(const float* __restrict__ S,
                                                 const float* __restrict__ gp)
{
    __shared__ float red[8];
    const long row = blockIdx.x;
    const float* s = S + row * NN;
    const int tid = threadIdx.x;
    const float g = *gp;

    float4 v = *(const float4*)&s[tid * 4];
    v.x *= g; v.y *= g; v.z *= g; v.w *= g;

    float m = fmaxf(fmaxf(v.x, v.y), fmaxf(v.z, v.w));
#pragma unroll
    for (int o = 16; o > 0; o >>= 1) m = fmaxf(m, __shfl_xor_sync(0xffffffffu, m, o));
    if ((tid & 31) == 0) red[tid >> 5] = m;
    __syncthreads();
    m = red[0];
#pragma unroll
    for (int i = 1; i < 8; i++) m = fmaxf(m, red[i]);
    __syncthreads();

    float e0 = __expf(v.x - m), e1 = __expf(v.y - m);
    float e2 = __expf(v.z - m), e3 = __expf(v.w - m);
    float sum = (e0 + e1) + (e2 + e3);
#pragma unroll
    for (int o = 16; o > 0; o >>= 1) sum += __shfl_xor_sync(0xffffffffu, sum, o);
    if ((tid & 31) == 0) red[tid >> 5] = sum;
    __syncthreads();
    sum = ((red[0] + red[1]) + (red[2] + red[3])) +
          ((red[4] + red[5]) + (red[6] + red[7]));
    float r = 1.0f / sum;
    float a0 = e0 * r, a1 = e1 * r, a2 = e2 * r, a3 = e3 * r;

    u32 h0 = pack_bf2(a0, a1), h1 = pack_bf2(a2, a3);
    u32 l0 = pack_bf2(a0 - bflo(h0), a1 - bfhi(h0));
    u32 l1 = pack_bf2(a2 - bflo(h1), a3 - bfhi(h1));
    long off = row * NN + tid * 4;
    *(uint2*)(&g_ah[off]) = make_uint2(h0, h1);
    *(uint2*)(&g_al[off]) = make_uint2(l0, l1);
}

// ---------------------------------------------------------------------------
// g_mma: g[d][t] = sum_n f[d][n] alpha[t][n].  CTA 128d x 64t, 32 chunks.
// 128 threads / 4 warps tiled 2x2, warp tile 64d x 32t (A red 2x, B red 2x).
// A = f fp32 LDG+split8 (SW64); B = alpha planes via cp.async (SW64)
// ---------------------------------------------------------------------------
__global__ __launch_bounds__(128) void g_mma(const float* __restrict__ F)
{
    __shared__ __align__(16) char sm[2][STG];
    const int b  = blockIdx.z;
    const int d0 = blockIdx.x * 128;
    const float* Fb = F + ((long)b * DFE + d0) * NN;
    const __nv_bfloat16* Ahb = g_ah + (long)b * TT * NN;
    const __nv_bfloat16* Alb = g_al + (long)b * TT * NN;
    const int tid = threadIdx.x;
    const int warp = tid >> 5, l = tid & 31;
    const int wm = warp >> 1, wn = warp & 1;   // 2x2
    const u32 smb = smem_u32(sm);

    float4 rf[8];
    float acc[4][4][4] = {};

    auto ldg_f = [&](int nc) {
#pragma unroll
        for (int it = 0; it < 4; it++) {
            int i = it * 128 + tid;
            int r = i >> 2, grp = i & 3;
            const float* src = &Fb[(long)r * NN + nc + grp * 8];
            rf[it * 2]     = *(const float4*)src;
            rf[it * 2 + 1] = *(const float4*)(src + 4);
        }
    };
    auto sts_f = [&](int st) {
        char* base = sm[st];
#pragma unroll
        for (int it = 0; it < 4; it++) {
            int i = it * 128 + tid;
            int r = i >> 2, grp = i & 3;
            uint4 hv, lv;
            split8(rf[it * 2], rf[it * 2 + 1], hv, lv);
            u32 off = r * 64 + ((grp ^ ((r >> 1) & 3)) << 4);
            *(uint4*)(base + off)        = hv;
            *(uint4*)(base + off + 8192) = lv;
        }
    };
    auto cp_a = [&](int st, int nc) {
        u32 sb_ = smb + st * STG;
#pragma unroll
        for (int it = 0; it < 2; it++) {
            int i = it * 128 + tid;
            int r = i >> 2, gq = i & 3;
            u32 dst = sb_ + 16384 + r * 64 + ((gq ^ ((r >> 1) & 3)) << 4);
            long src = (long)r * NN + nc + gq * 8;
            cp16(dst,        &Ahb[src]);
            cp16(dst + 4096, &Alb[src]);
        }
        CP_COMMIT();
    };

    ldg_f(0);
    cp_a(0, 0);
    for (int ch = 0; ch < NN / 32; ch++) {
        int st = ch & 1;
        sts_f(st);
        if (ch + 1 < NN / 32) {
            ldg_f((ch + 1) * 32);
            cp_a(st ^ 1, (ch + 1) * 32);
            CP_WAIT1();
        } else CP_WAIT0();
        __syncthreads();
        u32 ab = smb + st * STG;
#pragma unroll
        for (int kk = 0; kk < 2; kk++) {
            u32 Ah[4][4], Alo[4][4], Bh[2][4], Bl[2][4];
#pragma unroll
            for (int mf = 0; mf < 4; mf++) {
                int r = wm * 64 + mf * 16 + (l & 7) + ((l >> 3) & 1) * 8;
                int cA = kk * 2 + (l >> 4);
                u32 off = r * 64 + ((cA ^ ((r >> 1) & 3)) << 4);
                ldsm4(Ah[mf],  ab + off);
                ldsm4(Alo[mf], ab + 8192 + off);
            }
#pragma unroll
            for (int nf2 = 0; nf2 < 2; nf2++) {
                int rB = wn * 32 + nf2 * 16 + ((l >> 4) & 1) * 8 + (l & 7);
                int cB = kk * 2 + ((l >> 3) & 1);
                u32 offb = rB * 64 + ((cB ^ ((rB >> 1) & 3)) << 4);
                ldsm4(Bh[nf2], ab + 16384 + offb);
                ldsm4(Bl[nf2], ab + 20480 + offb);
            }
#pragma unroll
            for (int mf = 0; mf < 4; mf++)
#pragma unroll
                for (int nf = 0; nf < 4; nf++) {
                    int n2 = nf >> 1, j = nf & 1;
                    mma_bf16(acc[mf][nf], Ah[mf],  &Bh[n2][j * 2]);
                    mma_bf16(acc[mf][nf], Ah[mf],  &Bl[n2][j * 2]);
                    mma_bf16(acc[mf][nf], Alo[mf], &Bh[n2][j * 2]);
                }
        }
        __syncthreads();
    }

    const int g8 = l >> 2, tig = l & 3;
#pragma unroll
    for (int mf = 0; mf < 4; mf++)
#pragma unroll
        for (int nf = 0; nf < 4; nf++) {
            int dd = d0 + wm * 64 + mf * 16 + g8;
            int t  = wn * 32 + nf * 8 + tig * 2;
            long off = ((long)b * DFE + dd) * TT + t;
            u32 h = pack_bf2(acc[mf][nf][0], acc[mf][nf][1]);
            u32 lo = pack_bf2(acc[mf][nf][0] - bflo(h),
                              acc[mf][nf][1] - bfhi(h));
            *(u32*)(&g_gh[off]) = h;
            *(u32*)(&g_gl[off]) = lo;
            long off2 = off + 8 * TT;
            u32 h2 = pack_bf2(acc[mf][nf][2], acc[mf][nf][3]);
            u32 lo2 = pack_bf2(acc[mf][nf][2] - bflo(h2),
                               acc[mf][nf][3] - bfhi(h2));
            *(u32*)(&g_gh[off2]) = h2;
            *(u32*)(&g_gl[off2]) = lo2;
        }
}

// ---------------------------------------------------------------------------
// c_mma: c[m][t] = sum_d wt[m][d] g[d][t] + bias[m].  CTA 128m x 64t.
// A = wt planes (SW64); B = g planes (SW128 trans). All cp.async.
// ---------------------------------------------------------------------------
__global__ __launch_bounds__(256) void c_mma(const float* __restrict__ bias,
                                             float* __restrict__ C)
{
    __shared__ __align__(16) char sm[2][STG];
    const int b  = blockIdx.z;
    const int m0 = blockIdx.x * 128;
    const __nv_bfloat16* Ghb = g_gh + (long)b * DFE * TT;
    const __nv_bfloat16* Glb = g_gl + (long)b * DFE * TT;
    const int tid = threadIdx.x;
    const int warp = tid >> 5, l = tid & 31;
    const int wm = warp >> 1, wn = warp & 1;
    const u32 smb = smem_u32(sm);

    float acc[2][4][4] = {};

    auto cp_issue = [&](int st, int dc) {
        u32 sb_ = smb + st * STG;
#pragma unroll
        for (int it = 0; it < 2; it++) {
            int i = it * 256 + tid;
            int r = i >> 2, gq = i & 3;
            u32 dst = sb_ + r * 64 + ((gq ^ ((r >> 1) & 3)) << 4);
            long src = (long)(m0 + r) * DFE + dc + gq * 8;
            cp16(dst,        &g_wth[src]);
            cp16(dst + 8192, &g_wtl[src]);
        }
        {
            int k = tid >> 3, g = tid & 7;
            u32 dst = sb_ + 16384 + k * 128 + ((g ^ (k & 7)) << 4);
            long src = (long)(dc + k) * TT + g * 8;
            cp16(dst,        &Ghb[src]);
            cp16(dst + 4096, &Glb[src]);
        }
        CP_COMMIT();
    };

    cp_issue(0, 0);
    for (int ch = 0; ch < DFE / 32; ch++) {
        int st = ch & 1;
        if (ch + 1 < DFE / 32) { cp_issue(st ^ 1, (ch + 1) * 32); CP_WAIT1(); }
        else CP_WAIT0();
        __syncthreads();
        u32 ab = smb + st * STG;
#pragma unroll
        for (int kk = 0; kk < 2; kk++) {
            u32 Ah[2][4], Alo[2][4], Bh[2][4], Bl[2][4];
#pragma unroll
            for (int mf = 0; mf < 2; mf++) {
                int r = wm * 32 + mf * 16 + (l & 7) + ((l >> 3) & 1) * 8;
                int cA = kk * 2 + (l >> 4);
                u32 off = r * 64 + ((cA ^ ((r >> 1) & 3)) << 4);
                ldsm4(Ah[mf],  ab + off);
                ldsm4(Alo[mf], ab + 8192 + off);
            }
            int rB = kk * 16 + (l & 7) + ((l >> 3) & 1) * 8;
#pragma unroll
            for (int nf2 = 0; nf2 < 2; nf2++) {
                int cB = wn * 4 + nf2 * 2 + (l >> 4);
                u32 offb = rB * 128 + ((cB ^ (rB & 7)) << 4);
                ldsm4t(Bh[nf2], ab + 16384 + offb);
                ldsm4t(Bl[nf2], ab + 20480 + offb);
            }
#pragma unroll
            for (int mf = 0; mf < 2; mf++)
#pragma unroll
                for (int nf = 0; nf < 4; nf++) {
                    int n2 = nf >> 1, j = nf & 1;
                    mma_bf16(acc[mf][nf], Ah[mf],  &Bh[n2][j * 2]);
                    mma_bf16(acc[mf][nf], Ah[mf],  &Bl[n2][j * 2]);
                    mma_bf16(acc[mf][nf], Alo[mf], &Bh[n2][j * 2]);
                }
        }
        __syncthreads();
    }

    const int g8 = l >> 2, tig = l & 3;
#pragma unroll
    for (int mf = 0; mf < 2; mf++) {
        int row = wm * 32 + mf * 16 + g8;
        float bi0 = bias[m0 + row], bi1 = bias[m0 + row + 8];
#pragma unroll
        for (int nf = 0; nf < 4; nf++) {
            int t0 = wn * 32 + nf * 8 + tig * 2;
            float* p = &C[((long)b * KK + m0 + row) * TT + t0];
            *(float2*)p = make_float2(acc[mf][nf][0] + bi0, acc[mf][nf][1] + bi0);
            *(float2*)(p + 8 * TT) =
                make_float2(acc[mf][nf][2] + bi1, acc[mf][nf][3] + bi1);
        }
    }
}

// ---------------------------------------------------------------------------
// Finalize: norms + cos[b][i][j] = (sum_k c[k][i] e[k][j]) / (lc[i] le[j])
// ---------------------------------------------------------------------------
__global__ __launch_bounds__(256) void finalize_k(const float* __restrict__ Cm,
                                                  const float* __restrict__ E,
                                                  float* __restrict__ Out)
{
    __shared__ float rn[128];
    __shared__ float As[16][64];
    __shared__ float Bs[16][64];
    const int b = blockIdx.x;
    const float* cb = Cm + (long)b * KK * TT;
    const float* eb = E + (long)b * KK * TT;
    const int tid = threadIdx.x;

    if (tid < 128) {
        const float* p = (tid < 64) ? cb : eb;
        int t = tid & 63;
        float ss = 0.f;
        for (int k = 0; k < KK; k++) {
            float x = p[k * TT + t];
            ss = fmaf(x, x, ss);
        }
        rn[tid] = rsqrtf(ss);
    }

    const int tx = tid & 15, ty = tid >> 4;
    float acc[4][4] = {};
    for (int k0 = 0; k0 < KK; k0 += 16) {
        *(float4*)&As[ty][tx * 4] = *(const float4*)&cb[(k0 + ty) * TT + tx * 4];
        *(float4*)&Bs[ty][tx * 4] = *(const float4*)&eb[(k0 + ty) * TT + tx * 4];
        __syncthreads();
#pragma unroll
        for (int kk = 0; kk < 16; kk++) {
            float4 a4 = *(const float4*)&As[kk][ty * 4];
            float4 b4 = *(const float4*)&Bs[kk][tx * 4];
            float av[4] = {a4.x, a4.y, a4.z, a4.w};
            float bv[4] = {b4.x, b4.y, b4.z, b4.w};
#pragma unroll
            for (int i = 0; i < 4; i++)
#pragma unroll
                for (int j = 0; j < 4; j++) acc[i][j] = fmaf(av[i], bv[j], acc[i][j]);
        }
        __syncthreads();
    }

    float* ob = Out + (long)b * TT * TT;
#pragma unroll
    for (int i = 0; i < 4; i++) {
        int ii = ty * 4 + i;
        float ri = rn[ii];
        float4 o;
        o.x = acc[i][0] * ri * rn[64 + tx * 4 + 0];
        o.y = acc[i][1] * ri * rn[64 + tx * 4 + 1];
        o.z = acc[i][2] * ri * rn[64 + tx * 4 + 2];
        o.w = acc[i][3] * ri * rn[64 + tx * 4 + 3];
        *(float4*)&ob[ii * TT + tx * 4] = o;
    }
}

// ---------------------------------------------------------------------------
extern "C" void kernel_launch(void* const* d_in, const int* in_sizes, int n_in,
                              void* d_out, int out_size)
{
    const float* e  = (const float*)d_in[0];   // [B,K,T]
    const float* f  = (const float*)d_in[1];   // [B,DF,N]
    const float* gp = (const float*)d_in[2];   // scalar gamma
    const float* W  = (const float*)d_in[3];   // [DF,K]
    const float* bs = (const float*)d_in[4];   // [K]
    float* out = (float*)d_out;                // [B,T,T]

    float *ps, *pc;
    cudaGetSymbolAddress((void**)&ps, g_s);
    cudaGetSymbolAddress((void**)&pc, g_c);

    // 0) split W / W^T / e into bf16 hi-lo planes
    prep_w<<<DFE * KK / 256, 256>>>(W);
    prep_e<<<BB * KK * TT / 256, 256>>>(e);

    // 1) u' = (W e)^T -> split planes [B,T,DF]  (bias cancels in softmax)
    u_mma<<<dim3(DFE / 128, 1, BB), 256>>>();

    // 2) s = u' f : [B,T,N] fp32   (128-thread CTAs, 2x2 warp tiling)
    s_mma<<<dim3(NN / 128, 1, BB), 128>>>(f, ps);

    // 3) alpha = softmax(gamma * s) -> split planes
    softmax_k<<<BB * TT, 256>>>(ps, gp);

    // 4) g = f alpha^T -> split planes [B,DF,T]  (128-thread CTAs, 2x2)
    g_mma<<<dim3(DFE / 128, 1, BB), 128>>>(f);

    // 5) c = W^T g + b : [B,K,T] fp32  (Sum_n alpha = 1)
    c_mma<<<dim3(KK / 128, 1, BB), 256>>>(bs, pc);

    // 6) cos = (c^T e) / outer(|c|,|e|)
    finalize_k<<<64, 256>>>(pc, e, out);
}

// round 16
// speedup vs baseline: 1.8975x; 1.0115x over previous
#include <cuda_runtime.h>
#include <cuda_bf16.h>
#include <cstdint>

// Shapes (fixed by the problem)
constexpr int BB = 64;    // batch
constexpr int KK = 256;   // feature dim K
constexpr int TT = 64;    // word tokens
constexpr int DFE = 768;  // image channels
constexpr int NN = 1024;  // regions

// Scratch (device globals: allocation-free contract)
__device__ float g_s[BB * TT * NN];    // s (pre-softmax)  [B,T,N]
__device__ float g_c[BB * KK * TT];    // c                [B,K,T]
// pre-split bf16 hi/lo planes
__device__ __nv_bfloat16 g_wh[DFE * KK],  g_wl[DFE * KK];    // W    [DF,K]
__device__ __nv_bfloat16 g_wth[KK * DFE], g_wtl[KK * DFE];   // W^T  [K,DF]
__device__ __nv_bfloat16 g_uh[BB * TT * DFE], g_ul[BB * TT * DFE]; // u'
__device__ __nv_bfloat16 g_ah[BB * TT * NN], g_al[BB * TT * NN];   // alpha
__device__ __nv_bfloat16 g_gh[BB * DFE * TT], g_gl[BB * DFE * TT]; // g

typedef unsigned int u32;

// ---- helpers --------------------------------------------------------------
__device__ __forceinline__ u32 smem_u32(const void* p) {
    u32 a;
    asm("{ .reg .u64 t; cvta.to.shared.u64 t, %1; cvt.u32.u64 %0, t; }"
        : "=r"(a) : "l"(p));
    return a;
}
// pack (a->low16, b->high16) bf16x2
__device__ __forceinline__ u32 pack_bf2(float a, float b) {
    u32 r; asm("cvt.rn.bf16x2.f32 %0, %1, %2;" : "=r"(r) : "f"(b), "f"(a));
    return r;
}
__device__ __forceinline__ float bflo(u32 p) { return __uint_as_float(p << 16); }
__device__ __forceinline__ float bfhi(u32 p) { return __uint_as_float(p & 0xffff0000u); }

// split 8 consecutive fp32 (two float4) into bf16x2 hi/lo uint4
__device__ __forceinline__ void split8(float4 x0, float4 x1, uint4& h, uint4& l) {
    h.x = pack_bf2(x0.x, x0.y);
    h.y = pack_bf2(x0.z, x0.w);
    h.z = pack_bf2(x1.x, x1.y);
    h.w = pack_bf2(x1.z, x1.w);
    l.x = pack_bf2(x0.x - bflo(h.x), x0.y - bfhi(h.x));
    l.y = pack_bf2(x0.z - bflo(h.y), x0.w - bfhi(h.y));
    l.z = pack_bf2(x1.x - bflo(h.z), x1.y - bfhi(h.z));
    l.w = pack_bf2(x1.z - bflo(h.w), x1.w - bfhi(h.w));
}
__device__ __forceinline__ void st_split(__nv_bfloat16* H, __nv_bfloat16* L,
                                         long idx, float v) {
    __nv_bfloat16 h = __float2bfloat16(v);
    H[idx] = h;
    L[idx] = __float2bfloat16(v - __bfloat162float(h));
}

__device__ __forceinline__ void cp16(u32 dst, const void* src) {
    asm volatile("cp.async.ca.shared.global [%0], [%1], 16;"
                 :: "r"(dst), "l"(src));
}
#define CP_COMMIT() asm volatile("cp.async.commit_group;")
#define CP_WAIT1()  asm volatile("cp.async.wait_group 1;")
#define CP_WAIT0()  asm volatile("cp.async.wait_group 0;")

__device__ __forceinline__ void ldsm4(u32* r, u32 addr) {
    asm volatile("ldmatrix.sync.aligned.m8n8.x4.shared.b16 {%0,%1,%2,%3}, [%4];"
                 : "=r"(r[0]), "=r"(r[1]), "=r"(r[2]), "=r"(r[3]) : "r"(addr));
}
__device__ __forceinline__ void ldsm4t(u32* r, u32 addr) {
    asm volatile("ldmatrix.sync.aligned.m8n8.x4.trans.shared.b16 {%0,%1,%2,%3}, [%4];"
                 : "=r"(r[0]), "=r"(r[1]), "=r"(r[2]), "=r"(r[3]) : "r"(addr));
}
__device__ __forceinline__ void mma_bf16(float* d, const u32* a, const u32* b) {
    asm volatile(
        "mma.sync.aligned.m16n8k16.row.col.f32.bf16.bf16.f32 "
        "{%0,%1,%2,%3}, {%4,%5,%6,%7}, {%8,%9}, {%0,%1,%2,%3};"
        : "+f"(d[0]), "+f"(d[1]), "+f"(d[2]), "+f"(d[3])
        : "r"(a[0]), "r"(a[1]), "r"(a[2]), "r"(a[3]), "r"(b[0]), "r"(b[1]));
}

// Stage layout A8K+B4K kernels (u,c): Ah 0 | Al 8192 | Bh 16384 | Bl 20480
// Stage layout s_mma:                 Ah 0 | Al 4096 | Bh 8192(2x4K) | Bl 16384
constexpr int STG = 24576;

// ---------------------------------------------------------------------------
// prep_w: W [DF,K] -> split planes for W and W^T
// ---------------------------------------------------------------------------
__global__ void prep_w(const float* __restrict__ W) {
    int idx = blockIdx.x * 256 + threadIdx.x;   // DFE*KK
    int d = idx >> 8, k = idx & 255;
    float v = W[idx];
    __nv_bfloat16 h = __float2bfloat16(v);
    __nv_bfloat16 lo = __float2bfloat16(v - __bfloat162float(h));
    g_wh[idx] = h;  g_wl[idx] = lo;
    g_wth[k * DFE + d] = h;  g_wtl[k * DFE + d] = lo;
}

// ---------------------------------------------------------------------------
// u_mma: u[d][t] = sum_k W[d][k] e[k][t]; store split-transposed u'[t][d].
// CTA 128d x 64t, K chunks of 32. A (W planes) via cp.async; B = e read
// directly as fp32 and split in-register (prep_e fused away).
// ---------------------------------------------------------------------------
__global__ __launch_bounds__(256) void u_mma(const float* __restrict__ E)
{
    __shared__ __align__(16) char sm[2][STG];
    const int b = blockIdx.z;
    const int d0 = blockIdx.x * 128;
    const float* Eb = E + (long)b * KK * TT;
    const int tid = threadIdx.x;
    const int warp = tid >> 5, l = tid & 31;
    const int wm = warp >> 1, wn = warp & 1;
    const u32 smb = smem_u32(sm);

    float acc[2][4][4] = {};
    float4 re[2];

    auto cp_a = [&](int st, int k0) {
        u32 sb_ = smb + st * STG;
#pragma unroll
        for (int it = 0; it < 2; it++) {
            int i = it * 256 + tid;
            int r = i >> 2, gq = i & 3;
            u32 dst = sb_ + r * 64 + ((gq ^ ((r >> 1) & 3)) << 4);
            long src = (long)(d0 + r) * KK + k0 + gq * 8;
            cp16(dst,        &g_wh[src]);
            cp16(dst + 8192, &g_wl[src]);
        }
        CP_COMMIT();
    };
    auto ldg_e = [&](int k0) {
        int k = tid >> 3, seg = tid & 7;
        const float* src = &Eb[(long)(k0 + k) * TT + seg * 8];
        re[0] = *(const float4*)src;
        re[1] = *(const float4*)(src + 4);
    };
    auto sts_e = [&](int st) {
        char* base = sm[st];
        int k = tid >> 3, seg = tid & 7;
        uint4 hv, lv;
        split8(re[0], re[1], hv, lv);
        u32 off = 16384 + k * 128 + ((seg ^ (k & 7)) << 4);
        *(uint4*)(base + off)        = hv;
        *(uint4*)(base + off + 4096) = lv;
    };

    ldg_e(0);
    cp_a(0, 0);
    for (int ch = 0; ch < KK / 32; ch++) {
        int st = ch & 1;
        sts_e(st);
        if (ch + 1 < KK / 32) {
            ldg_e((ch + 1) * 32);
            cp_a(st ^ 1, (ch + 1) * 32);
            CP_WAIT1();
        } else CP_WAIT0();
        __syncthreads();
        u32 ab = smb + st * STG;
#pragma unroll
        for (int kk = 0; kk < 2; kk++) {
            u32 Ah[2][4], Alo[2][4], Bh[2][4], Bl[2][4];
#pragma unroll
            for (int mf = 0; mf < 2; mf++) {
                int r = wm * 32 + mf * 16 + (l & 7) + ((l >> 3) & 1) * 8;
                int cA = kk * 2 + (l >> 4);
                u32 off = r * 64 + ((cA ^ ((r >> 1) & 3)) << 4);
                ldsm4(Ah[mf],  ab + off);
                ldsm4(Alo[mf], ab + 8192 + off);
            }
            int rB = kk * 16 + (l & 7) + ((l >> 3) & 1) * 8;
#pragma unroll
            for (int nf2 = 0; nf2 < 2; nf2++) {
                int cB = wn * 4 + nf2 * 2 + (l >> 4);
                u32 offb = rB * 128 + ((cB ^ (rB & 7)) << 4);
                ldsm4t(Bh[nf2], ab + 16384 + offb);
                ldsm4t(Bl[nf2], ab + 20480 + offb);
            }
            // term-major order: adjacent mmas hit independent accumulators
#pragma unroll
            for (int mf = 0; mf < 2; mf++)
#pragma unroll
                for (int nf = 0; nf < 4; nf++)
                    mma_bf16(acc[mf][nf], Ah[mf],  &Bh[nf >> 1][(nf & 1) * 2]);
#pragma unroll
            for (int mf = 0; mf < 2; mf++)
#pragma unroll
                for (int nf = 0; nf < 4; nf++)
                    mma_bf16(acc[mf][nf], Ah[mf],  &Bl[nf >> 1][(nf & 1) * 2]);
#pragma unroll
            for (int mf = 0; mf < 2; mf++)
#pragma unroll
                for (int nf = 0; nf < 4; nf++)
                    mma_bf16(acc[mf][nf], Alo[mf], &Bh[nf >> 1][(nf & 1) * 2]);
        }
        __syncthreads();
    }

    const int g8 = l >> 2, tig = l & 3;
#pragma unroll
    for (int mf = 0; mf < 2; mf++)
#pragma unroll
        for (int nf = 0; nf < 4; nf++) {
            int m = wm * 32 + mf * 16 + g8;
            int t0 = wn * 32 + nf * 8 + tig * 2;
            long base_ = ((long)b * TT + t0) * DFE + d0 + m;
            st_split(g_uh, g_ul, base_,           acc[mf][nf][0]);
            st_split(g_uh, g_ul, base_ + DFE,     acc[mf][nf][1]);
            st_split(g_uh, g_ul, base_ + 8,       acc[mf][nf][2]);
            st_split(g_uh, g_ul, base_ + DFE + 8, acc[mf][nf][3]);
        }
}

// ---------------------------------------------------------------------------
// s_mma: s[t][n] = sum_d u'[t][d] f[d][n].  CTA 64t x 128n, 24 chunks of 32.
// 128 threads / 4 warps tiled 2x2 (R15 config). Term-major mma order.
// ---------------------------------------------------------------------------
__global__ __launch_bounds__(128) void s_mma(const float* __restrict__ F,
                                             float* __restrict__ S)
{
    __shared__ __align__(16) char sm[2][STG];
    const int b  = blockIdx.z;
    const int n0 = blockIdx.x * 128;
    const float* Fb = F + (long)b * DFE * NN;
    const __nv_bfloat16* Uhb = g_uh + (long)b * TT * DFE;
    const __nv_bfloat16* Ulb = g_ul + (long)b * TT * DFE;
    const int tid = threadIdx.x;
    const int warp = tid >> 5, l = tid & 31;
    const int wm = warp >> 1, wn = warp & 1;   // 2x2
    const u32 smb = smem_u32(sm);

    float4 rf[8];
    float acc[2][8][4] = {};

    auto ldg_f = [&](int dc) {
#pragma unroll
        for (int it = 0; it < 4; it++) {
            int i = it * 128 + tid;
            int k = i >> 4, grp = i & 15;
            const float* src = &Fb[(long)(dc + k) * NN + n0 + grp * 8];
            rf[it * 2]     = *(const float4*)src;
            rf[it * 2 + 1] = *(const float4*)(src + 4);
        }
    };
    auto sts_f = [&](int st) {
        char* base = sm[st];
#pragma unroll
        for (int it = 0; it < 4; it++) {
            int i = it * 128 + tid;
            int k = i >> 4, grp = i & 15;
            int sb2 = grp >> 3, g = grp & 7;
            uint4 hv, lv;
            split8(rf[it * 2], rf[it * 2 + 1], hv, lv);
            u32 off = 8192 + sb2 * 4096 + k * 128 + ((g ^ (k & 7)) << 4);
            *(uint4*)(base + off)        = hv;
            *(uint4*)(base + off + 8192) = lv;
        }
    };
    auto cp_u = [&](int st, int dc) {
        u32 sb_ = smb + st * STG;
#pragma unroll
        for (int it = 0; it < 2; it++) {
            int i = it * 128 + tid;
            int r = i >> 2, gq = i & 3;
            u32 dst = sb_ + r * 64 + ((gq ^ ((r >> 1) & 3)) << 4);
            long src = (long)r * DFE + dc + gq * 8;
            cp16(dst,        &Uhb[src]);
            cp16(dst + 4096, &Ulb[src]);
        }
        CP_COMMIT();
    };

    ldg_f(0);
    cp_u(0, 0);
    for (int ch = 0; ch < DFE / 32; ch++) {
        int st = ch & 1;
        sts_f(st);
        if (ch + 1 < DFE / 32) {
            ldg_f((ch + 1) * 32);
            cp_u(st ^ 1, (ch + 1) * 32);
            CP_WAIT1();
        } else CP_WAIT0();
        __syncthreads();
        u32 ab = smb + st * STG;
        u32 bb = ab + 8192 + wn * 4096;          // this warp's n64 sub-tile
#pragma unroll
        for (int kk = 0; kk < 2; kk++) {
            u32 Ah[2][4], Alo[2][4], Bh[4][4], Bl[4][4];
#pragma unroll
            for (int mf = 0; mf < 2; mf++) {
                int r = wm * 32 + mf * 16 + (l & 7) + ((l >> 3) & 1) * 8;
                int cA = kk * 2 + (l >> 4);
                u32 off = r * 64 + ((cA ^ ((r >> 1) & 3)) << 4);
                ldsm4(Ah[mf],  ab + off);
                ldsm4(Alo[mf], ab + 4096 + off);
            }
            int rB = kk * 16 + (l & 7) + ((l >> 3) & 1) * 8;
#pragma unroll
            for (int nf2 = 0; nf2 < 4; nf2++) {
                int cB = nf2 * 2 + (l >> 4);
                u32 offb = rB * 128 + ((cB ^ (rB & 7)) << 4);
                ldsm4t(Bh[nf2], bb + offb);
                ldsm4t(Bl[nf2], bb + 8192 + offb);
            }
            // term-major order: adjacent mmas hit independent accumulators
#pragma unroll
            for (int mf = 0; mf < 2; mf++)
#pragma unroll
                for (int nf = 0; nf < 8; nf++)
                    mma_bf16(acc[mf][nf], Ah[mf],  &Bh[nf >> 1][(nf & 1) * 2]);
#pragma unroll
            for (int mf = 0; mf < 2; mf++)
#pragma unroll
                for (int nf = 0; nf < 8; nf++)
                    mma_bf16(acc[mf][nf], Ah[mf],  &Bl[nf >> 1][(nf & 1) * 2]);
#pragma unroll
            for (int mf = 0; mf < 2; mf++)
#pragma unroll
                for (int nf = 0; nf < 8; nf++)
                    mma_bf16(acc[mf][nf], Alo[mf], &Bh[nf >> 1][(nf & 1) * 2]);
        }
        __syncthreads();
    }

    const int g8 = l >> 2, tig = l & 3;
#pragma unroll
    for (int mf = 0; mf < 2; mf++)
#pragma unroll
        for (int nf = 0; nf < 8; nf++) {
            int t = wm * 32 + mf * 16 + g8;
            int n = n0 + wn * 64 + nf * 8 + tig * 2;
            float* p = &S[((long)b * TT + t) * NN + n];
            *(float2*)p            = make_float2(acc[mf][nf][0], acc[mf][nf][1]);
            *(float2*)(p + 8 * NN) = make_float2(acc[mf][nf][2], acc[mf][nf][3]);
        }
}

// ---------------------------------------------------------------------------
// softmax: alpha = softmax(gamma*s) over N; write alpha as split bf16 planes.
// ---------------------------------------------------------------------------
__global__ __launch_bounds__(256) void softmax_k(const float* __restrict__ S,
                                                 const float* __restrict__ gp)
{
    __shared__ float red[8];
    const long row = blockIdx.x;
    const float* s = S + row * NN;
    const int tid = threadIdx.x;
    const float g = *gp;

    float4 v = *(const float4*)&s[tid * 4];
    v.x *= g; v.y *= g; v.z *= g; v.w *= g;

    float m = fmaxf(fmaxf(v.x, v.y), fmaxf(v.z, v.w));
#pragma unroll
    for (int o = 16; o > 0; o >>= 1) m = fmaxf(m, __shfl_xor_sync(0xffffffffu, m, o));
    if ((tid & 31) == 0) red[tid >> 5] = m;
    __syncthreads();
    m = red[0];
#pragma unroll
    for (int i = 1; i < 8; i++) m = fmaxf(m, red[i]);
    __syncthreads();

    float e0 = __expf(v.x - m), e1 = __expf(v.y - m);
    float e2 = __expf(v.z - m), e3 = __expf(v.w - m);
    float sum = (e0 + e1) + (e2 + e3);
#pragma unroll
    for (int o = 16; o > 0; o >>= 1) sum += __shfl_xor_sync(0xffffffffu, sum, o);
    if ((tid & 31) == 0) red[tid >> 5] = sum;
    __syncthreads();
    sum = ((red[0] + red[1]) + (red[2] + red[3])) +
          ((red[4] + red[5]) + (red[6] + red[7]));
    float r = 1.0f / sum;
    float a0 = e0 * r, a1 = e1 * r, a2 = e2 * r, a3 = e3 * r;

    u32 h0 = pack_bf2(a0, a1), h1 = pack_bf2(a2, a3);
    u32 l0 = pack_bf2(a0 - bflo(h0), a1 - bfhi(h0));
    u32 l1 = pack_bf2(a2 - bflo(h1), a3 - bfhi(h1));
    long off = row * NN + tid * 4;
    *(uint2*)(&g_ah[off]) = make_uint2(h0, h1);
    *(uint2*)(&g_al[off]) = make_uint2(l0, l1);
}

// ---------------------------------------------------------------------------
// g_mma: g[d][t] = sum_n f[d][n] alpha[t][n].  CTA 128d x 64t, 32 chunks.
// 128 threads / 4 warps tiled 2x2 (R15 config). Term-major mma order.
// ---------------------------------------------------------------------------
__global__ __launch_bounds__(128) void g_mma(const float* __restrict__ F)
{
    __shared__ __align__(16) char sm[2][STG];
    const int b  = blockIdx.z;
    const int d0 = blockIdx.x * 128;
    const float* Fb = F + ((long)b * DFE + d0) * NN;
    const __nv_bfloat16* Ahb = g_ah + (long)b * TT * NN;
    const __nv_bfloat16* Alb = g_al + (long)b * TT * NN;
    const int tid = threadIdx.x;
    const int warp = tid >> 5, l = tid & 31;
    const int wm = warp >> 1, wn = warp & 1;   // 2x2
    const u32 smb = smem_u32(sm);

    float4 rf[8];
    float acc[4][4][4] = {};

    auto ldg_f = [&](int nc) {
#pragma unroll
        for (int it = 0; it < 4; it++) {
            int i = it * 128 + tid;
            int r = i >> 2, grp = i & 3;
            const float* src = &Fb[(long)r * NN + nc + grp * 8];
            rf[it * 2]     = *(const float4*)src;
            rf[it * 2 + 1] = *(const float4*)(src + 4);
        }
    };
    auto sts_f = [&](int st) {
        char* base = sm[st];
#pragma unroll
        for (int it = 0; it < 4; it++) {
            int i = it * 128 + tid;
            int r = i >> 2, grp = i & 3;
            uint4 hv, lv;
            split8(rf[it * 2], rf[it * 2 + 1], hv, lv);
            u32 off = r * 64 + ((grp ^ ((r >> 1) & 3)) << 4);
            *(uint4*)(base + off)        = hv;
            *(uint4*)(base + off + 8192) = lv;
        }
    };
    auto cp_a = [&](int st, int nc) {
        u32 sb_ = smb + st * STG;
#pragma unroll
        for (int it = 0; it < 2; it++) {
            int i = it * 128 + tid;
            int r = i >> 2, gq = i & 3;
            u32 dst = sb_ + 16384 + r * 64 + ((gq ^ ((r >> 1) & 3)) << 4);
            long src = (long)r * NN + nc + gq * 8;
            cp16(dst,        &Ahb[src]);
            cp16(dst + 4096, &Alb[src]);
        }
        CP_COMMIT();
    };

    ldg_f(0);
    cp_a(0, 0);
    for (int ch = 0; ch < NN / 32; ch++) {
        int st = ch & 1;
        sts_f(st);
        if (ch + 1 < NN / 32) {
            ldg_f((ch + 1) * 32);
            cp_a(st ^ 1, (ch + 1) * 32);
            CP_WAIT1();
        } else CP_WAIT0();
        __syncthreads();
        u32 ab = smb + st * STG;
#pragma unroll
        for (int kk = 0; kk < 2; kk++) {
            u32 Ah[4][4], Alo[4][4], Bh[2][4], Bl[2][4];
#pragma unroll
            for (int mf = 0; mf < 4; mf++) {
                int r = wm * 64 + mf * 16 + (l & 7) + ((l >> 3) & 1) * 8;
                int cA = kk * 2 + (l >> 4);
                u32 off = r * 64 + ((cA ^ ((r >> 1) & 3)) << 4);
                ldsm4(Ah[mf],  ab + off);
                ldsm4(Alo[mf], ab + 8192 + off);
            }
#pragma unroll
            for (int nf2 = 0; nf2 < 2; nf2++) {
                int rB = wn * 32 + nf2 * 16 + ((l >> 4) & 1) * 8 + (l & 7);
                int cB = kk * 2 + ((l >> 3) & 1);
                u32 offb = rB * 64 + ((cB ^ ((rB >> 1) & 3)) << 4);
                ldsm4(Bh[nf2], ab + 16384 + offb);
                ldsm4(Bl[nf2], ab + 20480 + offb);
            }
            // term-major order: adjacent mmas hit independent accumulators
#pragma unroll
            for (int mf = 0; mf < 4; mf++)
#pragma unroll
                for (int nf = 0; nf < 4; nf++)
                    mma_bf16(acc[mf][nf], Ah[mf],  &Bh[nf >> 1][(nf & 1) * 2]);
#pragma unroll
            for (int mf = 0; mf < 4; mf++)
#pragma unroll
                for (int nf = 0; nf < 4; nf++)
                    mma_bf16(acc[mf][nf], Ah[mf],  &Bl[nf >> 1][(nf & 1) * 2]);
#pragma unroll
            for (int mf = 0; mf < 4; mf++)
#pragma unroll
                for (int nf = 0; nf < 4; nf++)
                    mma_bf16(acc[mf][nf], Alo[mf], &Bh[nf >> 1][(nf & 1) * 2]);
        }
        __syncthreads();
    }

    const int g8 = l >> 2, tig = l & 3;
#pragma unroll
    for (int mf = 0; mf < 4; mf++)
#pragma unroll
        for (int nf = 0; nf < 4; nf++) {
            int dd = d0 + wm * 64 + mf * 16 + g8;
            int t  = wn * 32 + nf * 8 + tig * 2;
            long off = ((long)b * DFE + dd) * TT + t;
            u32 h = pack_bf2(acc[mf][nf][0], acc[mf][nf][1]);
            u32 lo = pack_bf2(acc[mf][nf][0] - bflo(h),
                              acc[mf][nf][1] - bfhi(h));
            *(u32*)(&g_gh[off]) = h;
            *(u32*)(&g_gl[off]) = lo;
            long off2 = off + 8 * TT;
            u32 h2 = pack_bf2(acc[mf][nf][2], acc[mf][nf][3]);
            u32 lo2 = pack_bf2(acc[mf][nf][2] - bflo(h2),
                               acc[mf][nf][3] - bfhi(h2));
            *(u32*)(&g_gh[off2]) = h2;
            *(u32*)(&g_gl[off2]) = lo2;
        }
}

// ---------------------------------------------------------------------------
// c_mma: c[m][t] = sum_d wt[m][d] g[d][t] + bias[m].  CTA 128m x 64t.
// A = wt planes (SW64); B = g planes (SW128 trans). All cp.async.
// ---------------------------------------------------------------------------
__global__ __launch_bounds__(256) void c_mma(const float* __restrict__ bias,
                                             float* __restrict__ C)
{
    __shared__ __align__(16) char sm[2][STG];
    const int b  = blockIdx.z;
    const int m0 = blockIdx.x * 128;
    const __nv_bfloat16* Ghb = g_gh + (long)b * DFE * TT;
    const __nv_bfloat16* Glb = g_gl + (long)b * DFE * TT;
    const int tid = threadIdx.x;
    const int warp = tid >> 5, l = tid & 31;
    const int wm = warp >> 1, wn = warp & 1;
    const u32 smb = smem_u32(sm);

    float acc[2][4][4] = {};

    auto cp_issue = [&](int st, int dc) {
        u32 sb_ = smb + st * STG;
#pragma unroll
        for (int it = 0; it < 2; it++) {
            int i = it * 256 + tid;
            int r = i >> 2, gq = i & 3;
            u32 dst = sb_ + r * 64 + ((gq ^ ((r >> 1) & 3)) << 4);
            long src = (long)(m0 + r) * DFE + dc + gq * 8;
            cp16(dst,        &g_wth[src]);
            cp16(dst + 8192, &g_wtl[src]);
        }
        {
            int k = tid >> 3, g = tid & 7;
            u32 dst = sb_ + 16384 + k * 128 + ((g ^ (k & 7)) << 4);
            long src = (long)(dc + k) * TT + g * 8;
            cp16(dst,        &Ghb[src]);
            cp16(dst + 4096, &Glb[src]);
        }
        CP_COMMIT();
    };

    cp_issue(0, 0);
    for (int ch = 0; ch < DFE / 32; ch++) {
        int st = ch & 1;
        if (ch + 1 < DFE / 32) { cp_issue(st ^ 1, (ch + 1) * 32); CP_WAIT1(); }
        else CP_WAIT0();
        __syncthreads();
        u32 ab = smb + st * STG;
#pragma unroll
        for (int kk = 0; kk < 2; kk++) {
            u32 Ah[2][4], Alo[2][4], Bh[2][4], Bl[2][4];
#pragma unroll
            for (int mf = 0; mf < 2; mf++) {
                int r = wm * 32 + mf * 16 + (l & 7) + ((l >> 3) & 1) * 8;
                int cA = kk * 2 + (l >> 4);
                u32 off = r * 64 + ((cA ^ ((r >> 1) & 3)) << 4);
                ldsm4(Ah[mf],  ab + off);
                ldsm4(Alo[mf], ab + 8192 + off);
            }
            int rB = kk * 16 + (l & 7) + ((l >> 3) & 1) * 8;
#pragma unroll
            for (int nf2 = 0; nf2 < 2; nf2++) {
                int cB = wn * 4 + nf2 * 2 + (l >> 4);
                u32 offb = rB * 128 + ((cB ^ (rB & 7)) << 4);
                ldsm4t(Bh[nf2], ab + 16384 + offb);
                ldsm4t(Bl[nf2], ab + 20480 + offb);
            }
            // term-major order
#pragma unroll
            for (int mf = 0; mf < 2; mf++)
#pragma unroll
                for (int nf = 0; nf < 4; nf++)
                    mma_bf16(acc[mf][nf], Ah[mf],  &Bh[nf >> 1][(nf & 1) * 2]);
#pragma unroll
            for (int mf = 0; mf < 2; mf++)
#pragma unroll
                for (int nf = 0; nf < 4; nf++)
                    mma_bf16(acc[mf][nf], Ah[mf],  &Bl[nf >> 1][(nf & 1) * 2]);
#pragma unroll
            for (int mf = 0; mf < 2; mf++)
#pragma unroll
                for (int nf = 0; nf < 4; nf++)
                    mma_bf16(acc[mf][nf], Alo[mf], &Bh[nf >> 1][(nf & 1) * 2]);
        }
        __syncthreads();
    }

    const int g8 = l >> 2, tig = l & 3;
#pragma unroll
    for (int mf = 0; mf < 2; mf++) {
        int row = wm * 32 + mf * 16 + g8;
        float bi0 = bias[m0 + row], bi1 = bias[m0 + row + 8];
#pragma unroll
        for (int nf = 0; nf < 4; nf++) {
            int t0 = wn * 32 + nf * 8 + tig * 2;
            float* p = &C[((long)b * KK + m0 + row) * TT + t0];
            *(float2*)p = make_float2(acc[mf][nf][0] + bi0, acc[mf][nf][1] + bi0);
            *(float2*)(p + 8 * TT) =
                make_float2(acc[mf][nf][2] + bi1, acc[mf][nf][3] + bi1);
        }
    }
}

// ---------------------------------------------------------------------------
// Finalize: norms + cos[b][i][j] = (sum_k c[k][i] e[k][j]) / (lc[i] le[j])
// ---------------------------------------------------------------------------
__global__ __launch_bounds__(256) void finalize_k(const float* __restrict__ Cm,
                                                  const float* __restrict__ E,
                                                  float* __restrict__ Out)
{
    __shared__ float rn[128];
    __shared__ float As[16][64];
    __shared__ float Bs[16][64];
    const int b = blockIdx.x;
    const float* cb = Cm + (long)b * KK * TT;
    const float* eb = E + (long)b * KK * TT;
    const int tid = threadIdx.x;

    if (tid < 128) {
        const float* p = (tid < 64) ? cb : eb;
        int t = tid & 63;
        float ss = 0.f;
        for (int k = 0; k < KK; k++) {
            float x = p[k * TT + t];
            ss = fmaf(x, x, ss);
        }
        rn[tid] = rsqrtf(ss);
    }

    const int tx = tid & 15, ty = tid >> 4;
    float acc[4][4] = {};
    for (int k0 = 0; k0 < KK; k0 += 16) {
        *(float4*)&As[ty][tx * 4] = *(const float4*)&cb[(k0 + ty) * TT + tx * 4];
        *(float4*)&Bs[ty][tx * 4] = *(const float4*)&eb[(k0 + ty) * TT + tx * 4];
        __syncthreads();
#pragma unroll
        for (int kk = 0; kk < 16; kk++) {
            float4 a4 = *(const float4*)&As[kk][ty * 4];
            float4 b4 = *(const float4*)&Bs[kk][tx * 4];
            float av[4] = {a4.x, a4.y, a4.z, a4.w};
            float bv[4] = {b4.x, b4.y, b4.z, b4.w};
#pragma unroll
            for (int i = 0; i < 4; i++)
#pragma unroll
                for (int j = 0; j < 4; j++) acc[i][j] = fmaf(av[i], bv[j], acc[i][j]);
        }
        __syncthreads();
    }

    float* ob = Out + (long)b * TT * TT;
#pragma unroll
    for (int i = 0; i < 4; i++) {
        int ii = ty * 4 + i;
        float ri = rn[ii];
        float4 o;
        o.x = acc[i][0] * ri * rn[64 + tx * 4 + 0];
        o.y = acc[i][1] * ri * rn[64 + tx * 4 + 1];
        o.z = acc[i][2] * ri * rn[64 + tx * 4 + 2];
        o.w = acc[i][3] * ri * rn[64 + tx * 4 + 3];
        *(float4*)&ob[ii * TT + tx * 4] = o;
    }
}

// ---------------------------------------------------------------------------
extern "C" void kernel_launch(void* const* d_in, const int* in_sizes, int n_in,
                              void* d_out, int out_size)
{
    const float* e  = (const float*)d_in[0];   // [B,K,T]
    const float* f  = (const float*)d_in[1];   // [B,DF,N]
    const float* gp = (const float*)d_in[2];   // scalar gamma
    const float* W  = (const float*)d_in[3];   // [DF,K]
    const float* bs = (const float*)d_in[4];   // [K]
    float* out = (float*)d_out;                // [B,T,T]

    float *ps, *pc;
    cudaGetSymbolAddress((void**)&ps, g_s);
    cudaGetSymbolAddress((void**)&pc, g_c);

    // 0) split W / W^T into bf16 hi-lo planes
    prep_w<<<DFE * KK / 256, 256>>>(W);

    // 1) u' = (W e)^T -> split planes [B,T,DF]  (e split fused in-kernel)
    u_mma<<<dim3(DFE / 128, 1, BB), 256>>>(e);

    // 2) s = u' f : [B,T,N] fp32
    s_mma<<<dim3(NN / 128, 1, BB), 128>>>(f, ps);

    // 3) alpha = softmax(gamma * s) -> split planes
    softmax_k<<<BB * TT, 256>>>(ps, gp);

    // 4) g = f alpha^T -> split planes [B,DF,T]
    g_mma<<<dim3(DFE / 128, 1, BB), 128>>>(f);

    // 5) c = W^T g + b : [B,K,T] fp32  (Sum_n alpha = 1)
    c_mma<<<dim3(KK / 128, 1, BB), 256>>>(bs, pc);

    // 6) cos = (c^T e) / outer(|c|,|e|)
    finalize_k<<<64, 256>>>(pc, e, out);
}